// round 2
// baseline (speedup 1.0000x reference)
#include <cuda_runtime.h>
#include <cuda_bf16.h>
#include <math.h>

// Problem constants (fixed shapes per reference)
#define DD 128
#define MAX_N1 50000
#define MAX_N2 50000
#define MAX_N0 100000

// ---------------- scratch (device globals; no allocation allowed) ----------------
__device__ float g_msg1 [MAX_N1 * DD];   // msg_1 -> net_msg1 (in place)
__device__ float g_msg2 [MAX_N2 * DD];   // msg_2 -> net_msg2 (in place)
__device__ float g_msg2b[MAX_N2 * DD];   // msg_2b -> net_2b (in place)
__device__ float g_cnt1 [MAX_N1];
__device__ float g_cnt2 [MAX_N2];
__device__ float g_cnt2b[MAX_N2];
__device__ float g_s1 [MAX_N0 * DD];     // s1s accum -> relu(linear) in place
__device__ float g_s2 [MAX_N0 * DD];
__device__ float g_s12[MAX_N0 * DD];
__device__ float g_c1 [MAX_N0];
__device__ float g_c2 [MAX_N0];
__device__ float g_c12[MAX_N0];

// ---------------- generic edge scatter: out[sidx[e]] += feat[gidx[e]] * (ew?ew[e]:1) ----------------
// one warp per edge, float4 per lane, vectorized red.global.add.v4.f32
__global__ void k_scatter(const float* __restrict__ feat,
                          const int*   __restrict__ gidx,
                          const int*   __restrict__ sidx,
                          const float* __restrict__ ew,
                          float* __restrict__ out,
                          float* __restrict__ cnt,
                          int E)
{
    int t = blockIdx.x * blockDim.x + threadIdx.x;
    int e = t >> 5;
    int lane = t & 31;
    if (e >= E) return;
    int g = __ldg(gidx + e);
    int s = __ldg(sidx + e);
    float4 v = __ldg((const float4*)(feat + (size_t)g * DD) + lane);
    if (ew) {
        float w = __ldg(ew + e);
        v.x *= w; v.y *= w; v.z *= w; v.w *= w;
    }
    float* op = out + (size_t)s * DD + lane * 4;
    asm volatile("red.global.add.v4.f32 [%0], {%1,%2,%3,%4};"
                 :: "l"(op), "f"(v.x), "f"(v.y), "f"(v.z), "f"(v.w) : "memory");
    if (lane == 0) atomicAdd(cnt + s, 1.0f);
}

// ---------------- finalize: msg = (msg / max(cnt,1) + xb) * 0.5, in place ----------------
__global__ void k_finalize(float* __restrict__ msg,
                           const float* __restrict__ cnt,
                           const float* __restrict__ xb,
                           int N)
{
    int t = blockIdx.x * blockDim.x + threadIdx.x; // one float4 per thread
    if (t >= N * (DD / 4)) return;
    int node = t >> 5;
    float c = cnt[node];
    float inv = 1.0f / (c > 1.0f ? c : 1.0f);
    float4 m = ((const float4*)msg)[t];
    float4 x = __ldg(((const float4*)xb) + t);
    m.x = (m.x * inv + x.x) * 0.5f;
    m.y = (m.y * inv + x.y) * 0.5f;
    m.z = (m.z * inv + x.z) * 0.5f;
    m.w = (m.w * inv + x.w) * 0.5f;
    ((float4*)msg)[t] = m;
}

// ---------------- GEMM: y = relu((x / max(cnt,1)) @ W^T + b), in place ----------------
// block: 32x8 threads, tile 64 rows x 128 cols; W transposed into padded smem.
#define GEMM_SMEM (64 * 128 * 4 + 129 * 128 * 4)
__global__ void k_gemm_relu(float* __restrict__ xio,
                            const float* __restrict__ cnt,
                            const float* __restrict__ W,
                            const float* __restrict__ bias,
                            int N)
{
    extern __shared__ float sm[];
    float* xs = sm;              // [64][128]
    float* ws = sm + 64 * 128;   // [128][129] : ws[k*129 + i] = W[i][k]
    int tx = threadIdx.x;        // 0..31
    int ty = threadIdx.y;        // 0..7
    int tid = ty * 32 + tx;
    int row0 = blockIdx.x * 64;

    // load W transposed (padded pitch 129 -> conflict-free)
    for (int idx = tid; idx < 128 * 128; idx += 256) {
        int i = idx >> 7, k = idx & 127;
        ws[k * 129 + i] = __ldg(W + idx);
    }
    // load x tile, fused divide-by-count
    for (int idx = tid; idx < 64 * 32; idx += 256) {  // float4 granularity
        int r = idx >> 5;
        int row = row0 + r;
        float4 v = make_float4(0.f, 0.f, 0.f, 0.f);
        if (row < N) {
            float c = __ldg(cnt + row);
            float inv = 1.0f / (c > 1.0f ? c : 1.0f);
            v = ((const float4*)(xio + (size_t)row * DD))[idx & 31];
            v.x *= inv; v.y *= inv; v.z *= inv; v.w *= inv;
        }
        ((float4*)xs)[idx] = v;
    }
    __syncthreads();

    float acc[8][4];
#pragma unroll
    for (int r = 0; r < 8; r++) {
        acc[r][0] = 0.f; acc[r][1] = 0.f; acc[r][2] = 0.f; acc[r][3] = 0.f;
    }

#pragma unroll 4
    for (int k = 0; k < 128; k++) {
        float b0 = ws[k * 129 + tx];
        float b1 = ws[k * 129 + tx + 32];
        float b2 = ws[k * 129 + tx + 64];
        float b3 = ws[k * 129 + tx + 96];
#pragma unroll
        for (int r = 0; r < 8; r++) {
            float a = xs[(ty * 8 + r) * 128 + k];
            acc[r][0] += a * b0;
            acc[r][1] += a * b1;
            acc[r][2] += a * b2;
            acc[r][3] += a * b3;
        }
    }

    float bb0 = __ldg(bias + tx);
    float bb1 = __ldg(bias + tx + 32);
    float bb2 = __ldg(bias + tx + 64);
    float bb3 = __ldg(bias + tx + 96);
#pragma unroll
    for (int r = 0; r < 8; r++) {
        int row = row0 + ty * 8 + r;
        if (row < N) {
            float* yr = xio + (size_t)row * DD;
            yr[tx]      = fmaxf(acc[r][0] + bb0, 0.f);
            yr[tx + 32] = fmaxf(acc[r][1] + bb1, 0.f);
            yr[tx + 64] = fmaxf(acc[r][2] + bb2, 0.f);
            yr[tx + 96] = fmaxf(acc[r][3] + bb3, 0.f);
        }
    }
}

// ---------------- attention combine: softmax over 3 metapath scores ----------------
__global__ void k_att(const float* __restrict__ y1,
                      const float* __restrict__ y2,
                      const float* __restrict__ y3,
                      const float* __restrict__ att,
                      float* __restrict__ out,
                      int N)
{
    int t = blockIdx.x * blockDim.x + threadIdx.x;
    int n = t >> 5;
    int lane = t & 31;
    if (n >= N) return;
    size_t base = (size_t)n * DD;
    float4 v1 = __ldg((const float4*)(y1 + base) + lane);
    float4 v2 = __ldg((const float4*)(y2 + base) + lane);
    float4 v3 = __ldg((const float4*)(y3 + base) + lane);
    float4 a1 = __ldg((const float4*)att + lane);
    float4 a2 = __ldg((const float4*)att + 32 + lane);
    float4 a3 = __ldg((const float4*)att + 64 + lane);

    float s1 = v1.x * a1.x + v1.y * a1.y + v1.z * a1.z + v1.w * a1.w;
    float s2 = v2.x * a2.x + v2.y * a2.y + v2.z * a2.z + v2.w * a2.w;
    float s3 = v3.x * a3.x + v3.y * a3.y + v3.z * a3.z + v3.w * a3.w;
#pragma unroll
    for (int off = 16; off; off >>= 1) {
        s1 += __shfl_xor_sync(0xFFFFFFFFu, s1, off);
        s2 += __shfl_xor_sync(0xFFFFFFFFu, s2, off);
        s3 += __shfl_xor_sync(0xFFFFFFFFu, s3, off);
    }
    float m = fmaxf(s1, fmaxf(s2, s3));
    float e1 = __expf(s1 - m), e2 = __expf(s2 - m), e3 = __expf(s3 - m);
    float inv = 1.0f / (e1 + e2 + e3);
    float w1 = e1 * inv, w2 = e2 * inv, w3 = e3 * inv;

    float4 o;
    o.x = w1 * v1.x + w2 * v2.x + w3 * v3.x;
    o.y = w1 * v1.y + w2 * v2.y + w3 * v3.y;
    o.z = w1 * v1.z + w2 * v2.z + w3 * v3.z;
    o.w = w1 * v1.w + w2 * v2.w + w3 * v3.w;
    ((float4*)(out + base))[lane] = o;
}

// ---------------- launch ----------------
static inline int cdiv(long long a, int b) { return (int)((a + b - 1) / b); }

extern "C" void kernel_launch(void* const* d_in, const int* in_sizes, int n_in,
                              void* d_out, int out_size)
{
    const float* x_node   = (const float*)d_in[0];
    const float* x1       = (const float*)d_in[1];
    const float* x2       = (const float*)d_in[2];
    const int*   ei1_src  = (const int*)d_in[3];
    const int*   ei1_dst  = (const int*)d_in[4];
    const int*   ei2_src  = (const int*)d_in[5];
    const int*   ei2_dst  = (const int*)d_in[6];
    const int*   ei12_src = (const int*)d_in[7];
    const int*   ei12_dst = (const int*)d_in[8];
    const float* ew1      = (const float*)d_in[9];
    const float* ew2      = (const float*)d_in[10];
    const float* W1       = (const float*)d_in[11];
    const float* b1       = (const float*)d_in[12];
    const float* W2       = (const float*)d_in[13];
    const float* b2       = (const float*)d_in[14];
    const float* W12      = (const float*)d_in[15];
    const float* b12      = (const float*)d_in[16];
    const float* att      = (const float*)d_in[17];
    float* out = (float*)d_out;

    int n0  = in_sizes[0] / DD;
    int n1  = in_sizes[1] / DD;
    int n2  = in_sizes[2] / DD;
    int e1  = in_sizes[3];
    int e2  = in_sizes[5];
    int e12 = in_sizes[7];

    float *msg1, *msg2, *msg2b, *cnt1, *cnt2, *cnt2b;
    float *s1, *s2, *s12, *c1, *c2, *c12;
    cudaGetSymbolAddress((void**)&msg1,  g_msg1);
    cudaGetSymbolAddress((void**)&msg2,  g_msg2);
    cudaGetSymbolAddress((void**)&msg2b, g_msg2b);
    cudaGetSymbolAddress((void**)&cnt1,  g_cnt1);
    cudaGetSymbolAddress((void**)&cnt2,  g_cnt2);
    cudaGetSymbolAddress((void**)&cnt2b, g_cnt2b);
    cudaGetSymbolAddress((void**)&s1,  g_s1);
    cudaGetSymbolAddress((void**)&s2,  g_s2);
    cudaGetSymbolAddress((void**)&s12, g_s12);
    cudaGetSymbolAddress((void**)&c1,  g_c1);
    cudaGetSymbolAddress((void**)&c2,  g_c2);
    cudaGetSymbolAddress((void**)&c12, g_c12);

    cudaFuncSetAttribute(k_gemm_relu, cudaFuncAttributeMaxDynamicSharedMemorySize, GEMM_SMEM);

    // zero accumulators
    cudaMemsetAsync(msg1,  0, (size_t)n1 * DD * sizeof(float), 0);
    cudaMemsetAsync(msg2,  0, (size_t)n2 * DD * sizeof(float), 0);
    cudaMemsetAsync(msg2b, 0, (size_t)n2 * DD * sizeof(float), 0);
    cudaMemsetAsync(cnt1,  0, (size_t)n1 * sizeof(float), 0);
    cudaMemsetAsync(cnt2,  0, (size_t)n2 * sizeof(float), 0);
    cudaMemsetAsync(cnt2b, 0, (size_t)n2 * sizeof(float), 0);
    cudaMemsetAsync(s1,  0, (size_t)n0 * DD * sizeof(float), 0);
    cudaMemsetAsync(s2,  0, (size_t)n0 * DD * sizeof(float), 0);
    cudaMemsetAsync(s12, 0, (size_t)n0 * DD * sizeof(float), 0);
    cudaMemsetAsync(c1,  0, (size_t)n0 * sizeof(float), 0);
    cudaMemsetAsync(c2,  0, (size_t)n0 * sizeof(float), 0);
    cudaMemsetAsync(c12, 0, (size_t)n0 * sizeof(float), 0);

    const int BT = 256;

    // msg_1 = scatter_mean(x_node[ei1_src]*ew1, ei1_dst, N1)
    k_scatter<<<cdiv((long long)e1 * 32, BT), BT>>>(x_node, ei1_src, ei1_dst, ew1, msg1, cnt1, e1);
    // msg_2 = scatter_mean(x_node[ei2_src]*ew2, ei2_dst, N2)
    k_scatter<<<cdiv((long long)e2 * 32, BT), BT>>>(x_node, ei2_src, ei2_dst, ew2, msg2, cnt2, e2);
    // net_msg1 = (msg_1/cnt + x1)*0.5 ; net_msg2 likewise
    k_finalize<<<cdiv((long long)n1 * 32, BT), BT>>>(msg1, cnt1, x1, n1);
    k_finalize<<<cdiv((long long)n2 * 32, BT), BT>>>(msg2, cnt2, x2, n2);

    // s1s accum = scatter_sum(net_msg1[ei1_dst], ei1_src)
    k_scatter<<<cdiv((long long)e1 * 32, BT), BT>>>(msg1, ei1_dst, ei1_src, (const float*)0, s1, c1, e1);
    // s2s accum = scatter_sum(net_msg2[ei2_dst], ei2_src)
    k_scatter<<<cdiv((long long)e2 * 32, BT), BT>>>(msg2, ei2_dst, ei2_src, (const float*)0, s2, c2, e2);

    // msg_2b = scatter_mean(net_msg1[ei12_src], ei12_dst, N2)
    k_scatter<<<cdiv((long long)e12 * 32, BT), BT>>>(msg1, ei12_src, ei12_dst, (const float*)0, msg2b, cnt2b, e12);
    // net_2b = (msg_2b/cnt + x2)*0.5
    k_finalize<<<cdiv((long long)n2 * 32, BT), BT>>>(msg2b, cnt2b, x2, n2);
    // s12s accum = scatter_sum(net_2b[ei2_dst]*ew2, ei2_src)
    k_scatter<<<cdiv((long long)e2 * 32, BT), BT>>>(msg2b, ei2_dst, ei2_src, ew2, s12, c12, e2);

    // fused mean-divide + linear + relu (in place)
    dim3 gblk(32, 8);
    k_gemm_relu<<<cdiv(n0, 64), gblk, GEMM_SMEM>>>(s1,  c1,  W1,  b1,  n0);
    k_gemm_relu<<<cdiv(n0, 64), gblk, GEMM_SMEM>>>(s2,  c2,  W2,  b2,  n0);
    k_gemm_relu<<<cdiv(n0, 64), gblk, GEMM_SMEM>>>(s12, c12, W12, b12, n0);

    // attention combine
    k_att<<<cdiv((long long)n0 * 32, BT), BT>>>(s1, s2, s12, att, out, n0);
}

// round 3
// speedup vs baseline: 1.2008x; 1.2008x over previous
#include <cuda_runtime.h>
#include <cuda_bf16.h>
#include <math.h>

#define DD 128
#define N1CAP 50000
#define N2CAP 50000
#define N0CAP 100000

// ---------------- single scratch arena (one memset) ----------------
// layout (floats):
//   msg1   [N1CAP*128]
//   msg2   [N2CAP*128]
//   msg2b  [N2CAP*128]
//   s1     [N0CAP*128]
//   s2     [N0CAP*128]
//   s12    [N0CAP*128]
//   cnt1[N1CAP] cnt2[N2CAP] cnt2b[N2CAP] c1[N0CAP] c2[N0CAP]   (c12 == c2)
#define OFF_MSG1   0
#define OFF_MSG2   (OFF_MSG1 + N1CAP * DD)
#define OFF_MSG2B  (OFF_MSG2 + N2CAP * DD)
#define OFF_S1     (OFF_MSG2B + N2CAP * DD)
#define OFF_S2     (OFF_S1 + N0CAP * DD)
#define OFF_S12    (OFF_S2 + N0CAP * DD)
#define OFF_CNT1   (OFF_S12 + N0CAP * DD)
#define OFF_CNT2   (OFF_CNT1 + N1CAP)
#define OFF_CNT2B  (OFF_CNT2 + N2CAP)
#define OFF_C1     (OFF_CNT2B + N2CAP)
#define OFF_C2     (OFF_C1 + N0CAP)
#define SCRATCH_FLOATS (OFF_C2 + N0CAP)

__device__ float g_buf[SCRATCH_FLOATS];

// ---------------- scatter, 4 edges per warp (MLP=4) ----------------
// out[sidx[e]] += feat[gidx[e]] * (ew ? ew[e] : 1);  cnt[sidx[e]] += 1
__global__ void k_scatter4(const float* __restrict__ feat,
                           const int*   __restrict__ gidx,
                           const int*   __restrict__ sidx,
                           const float* __restrict__ ew,
                           float* __restrict__ out,
                           float* __restrict__ cnt,
                           int E)
{
    int t = blockIdx.x * blockDim.x + threadIdx.x;
    int w = t >> 5, lane = t & 31;
    int e0 = w << 2;
    if (e0 >= E) return;
    int n = E - e0; if (n > 4) n = 4;

    int g = 0, s = 0; float wt = 1.0f;
    int eu = e0 + lane;
    if (lane < 4 && eu < E) {
        g = __ldg(gidx + eu);
        s = __ldg(sidx + eu);
        if (ew) wt = __ldg(ew + eu);
    }

    float4 v[4];
#pragma unroll
    for (int u = 0; u < 4; u++) {
        int gu = __shfl_sync(0xffffffffu, g, u);
        if (u < n) v[u] = __ldg((const float4*)(feat + (size_t)gu * DD) + lane);
    }
#pragma unroll
    for (int u = 0; u < 4; u++) {
        if (u < n) {
            int   su = __shfl_sync(0xffffffffu, s, u);
            float ww = __shfl_sync(0xffffffffu, wt, u);
            float4 vv = v[u];
            vv.x *= ww; vv.y *= ww; vv.z *= ww; vv.w *= ww;
            float* op = out + (size_t)su * DD + lane * 4;
            asm volatile("red.global.add.v4.f32 [%0], {%1,%2,%3,%4};"
                         :: "l"(op), "f"(vv.x), "f"(vv.y), "f"(vv.z), "f"(vv.w)
                         : "memory");
        }
    }
    if (lane < n) atomicAdd(cnt + s, 1.0f);
}

// ---------------- fused dual scatter over ei2 (s2 unweighted, s12 weighted) ----------------
__global__ void k_scatter4_dual(const float* __restrict__ feat_a,  // net2
                                const float* __restrict__ feat_b,  // net2b
                                const int*   __restrict__ gidx,    // ei2_dst
                                const int*   __restrict__ sidx,    // ei2_src
                                const float* __restrict__ ew,      // ew2 (feat_b only)
                                float* __restrict__ out_a,         // s2
                                float* __restrict__ out_b,         // s12
                                float* __restrict__ cnt,           // c2 (shared)
                                int E)
{
    int t = blockIdx.x * blockDim.x + threadIdx.x;
    int w = t >> 5, lane = t & 31;
    int e0 = w << 2;
    if (e0 >= E) return;
    int n = E - e0; if (n > 4) n = 4;

    int g = 0, s = 0; float wt = 1.0f;
    int eu = e0 + lane;
    if (lane < 4 && eu < E) {
        g  = __ldg(gidx + eu);
        s  = __ldg(sidx + eu);
        wt = __ldg(ew + eu);
    }

    float4 va[4], vb[4];
#pragma unroll
    for (int u = 0; u < 4; u++) {
        int gu = __shfl_sync(0xffffffffu, g, u);
        if (u < n) {
            va[u] = __ldg((const float4*)(feat_a + (size_t)gu * DD) + lane);
            vb[u] = __ldg((const float4*)(feat_b + (size_t)gu * DD) + lane);
        }
    }
#pragma unroll
    for (int u = 0; u < 4; u++) {
        if (u < n) {
            int   su = __shfl_sync(0xffffffffu, s, u);
            float ww = __shfl_sync(0xffffffffu, wt, u);
            float* pa = out_a + (size_t)su * DD + lane * 4;
            float4 a = va[u];
            asm volatile("red.global.add.v4.f32 [%0], {%1,%2,%3,%4};"
                         :: "l"(pa), "f"(a.x), "f"(a.y), "f"(a.z), "f"(a.w) : "memory");
            float4 b = vb[u];
            b.x *= ww; b.y *= ww; b.z *= ww; b.w *= ww;
            float* pb = out_b + (size_t)su * DD + lane * 4;
            asm volatile("red.global.add.v4.f32 [%0], {%1,%2,%3,%4};"
                         :: "l"(pb), "f"(b.x), "f"(b.y), "f"(b.z), "f"(b.w) : "memory");
        }
    }
    if (lane < n) atomicAdd(cnt + s, 1.0f);
}

// ---------------- finalize: msg = (msg / max(cnt,1) + xb) * 0.5, in place ----------------
__global__ void k_finalize(float* __restrict__ msg,
                           const float* __restrict__ cnt,
                           const float* __restrict__ xb,
                           int N)
{
    int t = blockIdx.x * blockDim.x + threadIdx.x;
    if (t >= N * (DD / 4)) return;
    int node = t >> 5;
    float c = cnt[node];
    float inv = 1.0f / (c > 1.0f ? c : 1.0f);
    float4 m = ((const float4*)msg)[t];
    float4 x = __ldg(((const float4*)xb) + t);
    m.x = (m.x * inv + x.x) * 0.5f;
    m.y = (m.y * inv + x.y) * 0.5f;
    m.z = (m.z * inv + x.z) * 0.5f;
    m.w = (m.w * inv + x.w) * 0.5f;
    ((float4*)msg)[t] = m;
}

// ---------------- GEMM: y = relu((x / max(cnt,1)) @ W^T + b), in place, FFMA2 ----------------
#define GEMM_SMEM (64 * 128 * 4 + 129 * 128 * 4)

__device__ __forceinline__ void ffma2(unsigned long long& d, unsigned long long a,
                                      unsigned long long b) {
    asm("fma.rn.f32x2 %0, %1, %2, %0;" : "+l"(d) : "l"(a), "l"(b));
}
__device__ __forceinline__ unsigned long long pack2(float lo, float hi) {
    unsigned long long r;
    asm("mov.b64 %0, {%1, %2};" : "=l"(r) : "f"(lo), "f"(hi));
    return r;
}
__device__ __forceinline__ void unpack2(unsigned long long v, float& lo, float& hi) {
    asm("mov.b64 {%0, %1}, %2;" : "=f"(lo), "=f"(hi) : "l"(v));
}

__global__ void k_gemm_relu(float* __restrict__ xio,
                            const float* __restrict__ cnt,
                            const float* __restrict__ W,
                            const float* __restrict__ bias,
                            int N)
{
    extern __shared__ float sm[];
    float* xs = sm;              // [64][128]
    float* ws = sm + 64 * 128;   // [128][129] : ws[k*129 + i] = W[i][k]
    int tx = threadIdx.x;        // 0..31
    int ty = threadIdx.y;        // 0..7
    int tid = ty * 32 + tx;
    int row0 = blockIdx.x * 64;

    for (int idx = tid; idx < 128 * 128; idx += 256) {
        int i = idx >> 7, k = idx & 127;
        ws[k * 129 + i] = __ldg(W + idx);
    }
    for (int idx = tid; idx < 64 * 32; idx += 256) {
        int r = idx >> 5;
        int row = row0 + r;
        float4 v = make_float4(0.f, 0.f, 0.f, 0.f);
        if (row < N) {
            float c = __ldg(cnt + row);
            float inv = 1.0f / (c > 1.0f ? c : 1.0f);
            v = ((const float4*)(xio + (size_t)row * DD))[idx & 31];
            v.x *= inv; v.y *= inv; v.z *= inv; v.w *= inv;
        }
        ((float4*)xs)[idx] = v;
    }
    __syncthreads();

    unsigned long long accA[8], accB[8];  // pairs (tx,tx+32) and (tx+64,tx+96)
#pragma unroll
    for (int r = 0; r < 8; r++) { accA[r] = 0ull; accB[r] = 0ull; }

#pragma unroll 4
    for (int k = 0; k < 128; k++) {
        float b0 = ws[k * 129 + tx];
        float b1 = ws[k * 129 + tx + 32];
        float b2 = ws[k * 129 + tx + 64];
        float b3 = ws[k * 129 + tx + 96];
        unsigned long long bA = pack2(b0, b1);
        unsigned long long bB = pack2(b2, b3);
#pragma unroll
        for (int r = 0; r < 8; r++) {
            float a = xs[(ty * 8 + r) * 128 + k];
            unsigned long long aa = pack2(a, a);
            ffma2(accA[r], aa, bA);
            ffma2(accB[r], aa, bB);
        }
    }

    float bb0 = __ldg(bias + tx);
    float bb1 = __ldg(bias + tx + 32);
    float bb2 = __ldg(bias + tx + 64);
    float bb3 = __ldg(bias + tx + 96);
#pragma unroll
    for (int r = 0; r < 8; r++) {
        int row = row0 + ty * 8 + r;
        if (row < N) {
            float a0, a1, a2, a3;
            unpack2(accA[r], a0, a1);
            unpack2(accB[r], a2, a3);
            float* yr = xio + (size_t)row * DD;
            yr[tx]      = fmaxf(a0 + bb0, 0.f);
            yr[tx + 32] = fmaxf(a1 + bb1, 0.f);
            yr[tx + 64] = fmaxf(a2 + bb2, 0.f);
            yr[tx + 96] = fmaxf(a3 + bb3, 0.f);
        }
    }
}

// ---------------- attention combine ----------------
__global__ void k_att(const float* __restrict__ y1,
                      const float* __restrict__ y2,
                      const float* __restrict__ y3,
                      const float* __restrict__ att,
                      float* __restrict__ out,
                      int N)
{
    int t = blockIdx.x * blockDim.x + threadIdx.x;
    int n = t >> 5;
    int lane = t & 31;
    if (n >= N) return;
    size_t base = (size_t)n * DD;
    float4 v1 = __ldg((const float4*)(y1 + base) + lane);
    float4 v2 = __ldg((const float4*)(y2 + base) + lane);
    float4 v3 = __ldg((const float4*)(y3 + base) + lane);
    float4 a1 = __ldg((const float4*)att + lane);
    float4 a2 = __ldg((const float4*)att + 32 + lane);
    float4 a3 = __ldg((const float4*)att + 64 + lane);

    float s1 = v1.x * a1.x + v1.y * a1.y + v1.z * a1.z + v1.w * a1.w;
    float s2 = v2.x * a2.x + v2.y * a2.y + v2.z * a2.z + v2.w * a2.w;
    float s3 = v3.x * a3.x + v3.y * a3.y + v3.z * a3.z + v3.w * a3.w;
#pragma unroll
    for (int off = 16; off; off >>= 1) {
        s1 += __shfl_xor_sync(0xFFFFFFFFu, s1, off);
        s2 += __shfl_xor_sync(0xFFFFFFFFu, s2, off);
        s3 += __shfl_xor_sync(0xFFFFFFFFu, s3, off);
    }
    float m = fmaxf(s1, fmaxf(s2, s3));
    float e1 = __expf(s1 - m), e2 = __expf(s2 - m), e3 = __expf(s3 - m);
    float inv = 1.0f / (e1 + e2 + e3);
    float w1 = e1 * inv, w2 = e2 * inv, w3 = e3 * inv;

    float4 o;
    o.x = w1 * v1.x + w2 * v2.x + w3 * v3.x;
    o.y = w1 * v1.y + w2 * v2.y + w3 * v3.y;
    o.z = w1 * v1.z + w2 * v2.z + w3 * v3.z;
    o.w = w1 * v1.w + w2 * v2.w + w3 * v3.w;
    ((float4*)(out + base))[lane] = o;
}

// ---------------- launch ----------------
static inline int cdiv(long long a, int b) { return (int)((a + b - 1) / b); }

extern "C" void kernel_launch(void* const* d_in, const int* in_sizes, int n_in,
                              void* d_out, int out_size)
{
    const float* x_node   = (const float*)d_in[0];
    const float* x1       = (const float*)d_in[1];
    const float* x2       = (const float*)d_in[2];
    const int*   ei1_src  = (const int*)d_in[3];
    const int*   ei1_dst  = (const int*)d_in[4];
    const int*   ei2_src  = (const int*)d_in[5];
    const int*   ei2_dst  = (const int*)d_in[6];
    const int*   ei12_src = (const int*)d_in[7];
    const int*   ei12_dst = (const int*)d_in[8];
    const float* ew1      = (const float*)d_in[9];
    const float* ew2      = (const float*)d_in[10];
    const float* W1       = (const float*)d_in[11];
    const float* b1       = (const float*)d_in[12];
    const float* W2       = (const float*)d_in[13];
    const float* b2       = (const float*)d_in[14];
    const float* W12      = (const float*)d_in[15];
    const float* b12      = (const float*)d_in[16];
    const float* att      = (const float*)d_in[17];
    float* out = (float*)d_out;

    int n0  = in_sizes[0] / DD;
    int n1  = in_sizes[1] / DD;
    int n2  = in_sizes[2] / DD;
    int e1  = in_sizes[3];
    int e2  = in_sizes[5];
    int e12 = in_sizes[7];

    float* buf;
    cudaGetSymbolAddress((void**)&buf, g_buf);
    float* msg1  = buf + OFF_MSG1;
    float* msg2  = buf + OFF_MSG2;
    float* msg2b = buf + OFF_MSG2B;
    float* s1    = buf + OFF_S1;
    float* s2    = buf + OFF_S2;
    float* s12   = buf + OFF_S12;
    float* cnt1  = buf + OFF_CNT1;
    float* cnt2  = buf + OFF_CNT2;
    float* cnt2b = buf + OFF_CNT2B;
    float* c1    = buf + OFF_C1;
    float* c2    = buf + OFF_C2;

    cudaFuncSetAttribute(k_gemm_relu, cudaFuncAttributeMaxDynamicSharedMemorySize, GEMM_SMEM);

    // one memset for the whole arena
    cudaMemsetAsync(buf, 0, (size_t)SCRATCH_FLOATS * sizeof(float), 0);

    const int BT = 256;
    // threads for scatter4: one warp per 4 edges
    #define SC4_GRID(E) cdiv(((long long)(((E) + 3) / 4)) * 32, BT)

    // pass A: msg1 = scatter_sum(x_node[ei1_src]*ew1 -> ei1_dst); msg2 likewise
    k_scatter4<<<SC4_GRID(e1), BT>>>(x_node, ei1_src, ei1_dst, ew1, msg1, cnt1, e1);
    k_scatter4<<<SC4_GRID(e2), BT>>>(x_node, ei2_src, ei2_dst, ew2, msg2, cnt2, e2);
    // net1 / net2
    k_finalize<<<cdiv((long long)n1 * 32, BT), BT>>>(msg1, cnt1, x1, n1);
    k_finalize<<<cdiv((long long)n2 * 32, BT), BT>>>(msg2, cnt2, x2, n2);

    // pass B1: s1 += net1[ei1_dst] -> ei1_src ;  pass C: msg2b += net1[ei12_src] -> ei12_dst
    k_scatter4<<<SC4_GRID(e1), BT>>>(msg1, ei1_dst, ei1_src, (const float*)0, s1, c1, e1);
    k_scatter4<<<SC4_GRID(e12), BT>>>(msg1, ei12_src, ei12_dst, (const float*)0, msg2b, cnt2b, e12);
    // net2b
    k_finalize<<<cdiv((long long)n2 * 32, BT), BT>>>(msg2b, cnt2b, x2, n2);

    // fused pass B2: s2 += net2[ei2_dst]; s12 += net2b[ei2_dst]*ew2 ; both -> ei2_src, shared count
    k_scatter4_dual<<<SC4_GRID(e2), BT>>>(msg2, msg2b, ei2_dst, ei2_src, ew2, s2, s12, c2, e2);

    // fused mean-divide + linear + relu (in place); c12 == c2
    dim3 gblk(32, 8);
    k_gemm_relu<<<cdiv(n0, 64), gblk, GEMM_SMEM>>>(s1,  c1, W1,  b1,  n0);
    k_gemm_relu<<<cdiv(n0, 64), gblk, GEMM_SMEM>>>(s2,  c2, W2,  b2,  n0);
    k_gemm_relu<<<cdiv(n0, 64), gblk, GEMM_SMEM>>>(s12, c2, W12, b12, n0);

    // attention combine
    k_att<<<cdiv((long long)n0 * 32, BT), BT>>>(s1, s2, s12, att, out, n0);
}

// round 4
// speedup vs baseline: 1.5971x; 1.3300x over previous
#include <cuda_runtime.h>
#include <cuda_bf16.h>
#include <math.h>

#define DD 128
#define N0CAP 100000
#define N1CAP 50000
#define N2CAP 50000
#define E1CAP 1600000
#define E2CAP 1600000
#define E12CAP 800000

// ---------------- scratch: feature buffers ----------------
__device__ float g_net1 [N1CAP * DD];
__device__ float g_net2 [N2CAP * DD];
__device__ float g_net2b[N2CAP * DD];
__device__ float g_s1 [N0CAP * DD];
__device__ float g_s2 [N0CAP * DD];
__device__ float g_s12[N0CAP * DD];

// ---------------- CSR scratch ----------------
// 5 CSRs: 1: ei1 by dst (N1) | 2: ei2 by dst (N2) | B1: ei1 by src (N0)
//         C: ei12 by dst (N2) | B2: ei2 by src (N0)
#define RP1   0
#define RP2   (RP1 + N1CAP + 1)
#define RPB1  (RP2 + N2CAP + 1)
#define RPC   (RPB1 + N0CAP + 1)
#define RPB2  (RPC + N2CAP + 1)
#define RPTOT (RPB2 + N0CAP + 1)
__device__ int g_rowptr[RPTOT];
__device__ int g_cursor[RPTOT];   // doubles as histogram

__device__ int   g_p1g [E1CAP];  __device__ float g_p1w [E1CAP];
__device__ int   g_p2g [E2CAP];  __device__ float g_p2w [E2CAP];
__device__ int   g_pb1g[E1CAP];
__device__ int   g_pcg [E12CAP];
__device__ int   g_pb2g[E2CAP];  __device__ float g_pb2w[E2CAP];

// ---------------- histogram ----------------
__global__ void k_hist(const int* __restrict__ idx, int* __restrict__ hist, int E)
{
    int e = blockIdx.x * blockDim.x + threadIdx.x;
    if (e < E) atomicAdd(hist + __ldg(idx + e), 1);
}

// ---------------- fused exclusive scan over 5 segments (one block each) ----------------
struct Seg5 { int off[5]; int n[5]; };
__global__ void k_scan5(int* __restrict__ rowptr_base, int* __restrict__ cur_base, Seg5 segs)
{
    __shared__ int wsum[32];
    int off = segs.off[blockIdx.x];
    int N   = segs.n[blockIdx.x];
    int* hist = cur_base + off;     // counts in, cursor (prefix) out
    int* rp   = rowptr_base + off;

    int tid = threadIdx.x;                 // blockDim = 1024
    int per = (N + 1023) >> 10;
    int lo = tid * per; if (lo > N) lo = N;
    int hi = lo + per;  if (hi > N) hi = N;

    int sum = 0;
    for (int i = lo; i < hi; i++) sum += hist[i];

    int lane = tid & 31, wid = tid >> 5;
    int v = sum;
#pragma unroll
    for (int o = 1; o < 32; o <<= 1) {
        int t = __shfl_up_sync(0xffffffffu, v, o);
        if (lane >= o) v += t;
    }
    if (lane == 31) wsum[wid] = v;
    __syncthreads();
    if (wid == 0) {
        int s = wsum[lane];
#pragma unroll
        for (int o = 1; o < 32; o <<= 1) {
            int t = __shfl_up_sync(0xffffffffu, s, o);
            if (lane >= o) s += t;
        }
        wsum[lane] = s;
    }
    __syncthreads();
    int excl = (v - sum) + (wid ? wsum[wid - 1] : 0);

    int run = excl;
    for (int i = lo; i < hi; i++) {
        int c = hist[i];
        rp[i] = run;
        hist[i] = run;    // cursor = start position
        run += c;
    }
    if (tid == 1023) rp[N] = excl + sum;   // grand total
}

// ---------------- binning: perm[pos] = gather_idx (and weight) ----------------
__global__ void k_bin(const int*   __restrict__ sc_idx,
                      const int*   __restrict__ g_idx,
                      const float* __restrict__ ew,
                      int*  __restrict__ cursor,
                      int*  __restrict__ pg,
                      float* __restrict__ pw,
                      int E)
{
    int e = blockIdx.x * blockDim.x + threadIdx.x;
    if (e >= E) return;
    int b = __ldg(sc_idx + e);
    int p = atomicAdd(cursor + b, 1);
    pg[p] = __ldg(g_idx + e);
    if (pw) pw[p] = __ldg(ew + e);
}

// ---------------- gather with msg finalize: out = (mean + xb) * 0.5 ----------------
__global__ void k_gather_msg(const float* __restrict__ feat,
                             const int*   __restrict__ pg,
                             const float* __restrict__ pw,   // may be null (w=1)
                             const int*   __restrict__ rp,
                             const float* __restrict__ xb,
                             float* __restrict__ out,
                             int N)
{
    int t = blockIdx.x * blockDim.x + threadIdx.x;
    int n = t >> 5, lane = t & 31;
    if (n >= N) return;
    int start = __ldg(rp + n), end = __ldg(rp + n + 1);

    float4 acc = make_float4(0.f, 0.f, 0.f, 0.f);
    int j = start;
    for (; j + 4 <= end; j += 4) {
        int g0 = __ldg(pg + j), g1 = __ldg(pg + j + 1);
        int g2 = __ldg(pg + j + 2), g3 = __ldg(pg + j + 3);
        float w0 = 1.f, w1 = 1.f, w2 = 1.f, w3 = 1.f;
        if (pw) { w0 = __ldg(pw + j); w1 = __ldg(pw + j + 1);
                  w2 = __ldg(pw + j + 2); w3 = __ldg(pw + j + 3); }
        float4 v0 = __ldg((const float4*)(feat + (size_t)g0 * DD) + lane);
        float4 v1 = __ldg((const float4*)(feat + (size_t)g1 * DD) + lane);
        float4 v2 = __ldg((const float4*)(feat + (size_t)g2 * DD) + lane);
        float4 v3 = __ldg((const float4*)(feat + (size_t)g3 * DD) + lane);
        acc.x += v0.x * w0 + v1.x * w1 + v2.x * w2 + v3.x * w3;
        acc.y += v0.y * w0 + v1.y * w1 + v2.y * w2 + v3.y * w3;
        acc.z += v0.z * w0 + v1.z * w1 + v2.z * w2 + v3.z * w3;
        acc.w += v0.w * w0 + v1.w * w1 + v2.w * w2 + v3.w * w3;
    }
    for (; j < end; j++) {
        int g = __ldg(pg + j);
        float w = pw ? __ldg(pw + j) : 1.f;
        float4 v = __ldg((const float4*)(feat + (size_t)g * DD) + lane);
        acc.x += v.x * w; acc.y += v.y * w; acc.z += v.z * w; acc.w += v.w * w;
    }
    int deg = end - start;
    float inv = 1.0f / (deg > 1 ? (float)deg : 1.0f);
    float4 x = __ldg((const float4*)(xb + (size_t)n * DD) + lane);
    float4 o;
    o.x = (acc.x * inv + x.x) * 0.5f;
    o.y = (acc.y * inv + x.y) * 0.5f;
    o.z = (acc.z * inv + x.z) * 0.5f;
    o.w = (acc.w * inv + x.w) * 0.5f;
    ((float4*)(out + (size_t)n * DD))[lane] = o;
}

// ---------------- gather mean only: out = mean ----------------
__global__ void k_gather_s(const float* __restrict__ feat,
                           const int*   __restrict__ pg,
                           const int*   __restrict__ rp,
                           float* __restrict__ out,
                           int N)
{
    int t = blockIdx.x * blockDim.x + threadIdx.x;
    int n = t >> 5, lane = t & 31;
    if (n >= N) return;
    int start = __ldg(rp + n), end = __ldg(rp + n + 1);

    float4 acc = make_float4(0.f, 0.f, 0.f, 0.f);
    int j = start;
    for (; j + 4 <= end; j += 4) {
        int g0 = __ldg(pg + j), g1 = __ldg(pg + j + 1);
        int g2 = __ldg(pg + j + 2), g3 = __ldg(pg + j + 3);
        float4 v0 = __ldg((const float4*)(feat + (size_t)g0 * DD) + lane);
        float4 v1 = __ldg((const float4*)(feat + (size_t)g1 * DD) + lane);
        float4 v2 = __ldg((const float4*)(feat + (size_t)g2 * DD) + lane);
        float4 v3 = __ldg((const float4*)(feat + (size_t)g3 * DD) + lane);
        acc.x += v0.x + v1.x + v2.x + v3.x;
        acc.y += v0.y + v1.y + v2.y + v3.y;
        acc.z += v0.z + v1.z + v2.z + v3.z;
        acc.w += v0.w + v1.w + v2.w + v3.w;
    }
    for (; j < end; j++) {
        int g = __ldg(pg + j);
        float4 v = __ldg((const float4*)(feat + (size_t)g * DD) + lane);
        acc.x += v.x; acc.y += v.y; acc.z += v.z; acc.w += v.w;
    }
    int deg = end - start;
    float inv = 1.0f / (deg > 1 ? (float)deg : 1.0f);
    float4 o = make_float4(acc.x * inv, acc.y * inv, acc.z * inv, acc.w * inv);
    ((float4*)(out + (size_t)n * DD))[lane] = o;
}

// ---------------- dual gather over shared CSR: s2 (w=1) and s12 (w=ew) ----------------
__global__ void k_gather_dual(const float* __restrict__ feat_a,
                              const float* __restrict__ feat_b,
                              const int*   __restrict__ pg,
                              const float* __restrict__ pw,
                              const int*   __restrict__ rp,
                              float* __restrict__ out_a,
                              float* __restrict__ out_b,
                              int N)
{
    int t = blockIdx.x * blockDim.x + threadIdx.x;
    int n = t >> 5, lane = t & 31;
    if (n >= N) return;
    int start = __ldg(rp + n), end = __ldg(rp + n + 1);

    float4 aa = make_float4(0.f, 0.f, 0.f, 0.f);
    float4 ab = make_float4(0.f, 0.f, 0.f, 0.f);
    int j = start;
    for (; j + 2 <= end; j += 2) {
        int g0 = __ldg(pg + j), g1 = __ldg(pg + j + 1);
        float w0 = __ldg(pw + j), w1 = __ldg(pw + j + 1);
        float4 a0 = __ldg((const float4*)(feat_a + (size_t)g0 * DD) + lane);
        float4 b0 = __ldg((const float4*)(feat_b + (size_t)g0 * DD) + lane);
        float4 a1 = __ldg((const float4*)(feat_a + (size_t)g1 * DD) + lane);
        float4 b1 = __ldg((const float4*)(feat_b + (size_t)g1 * DD) + lane);
        aa.x += a0.x + a1.x; aa.y += a0.y + a1.y; aa.z += a0.z + a1.z; aa.w += a0.w + a1.w;
        ab.x += b0.x * w0 + b1.x * w1; ab.y += b0.y * w0 + b1.y * w1;
        ab.z += b0.z * w0 + b1.z * w1; ab.w += b0.w * w0 + b1.w * w1;
    }
    for (; j < end; j++) {
        int g = __ldg(pg + j);
        float w = __ldg(pw + j);
        float4 a = __ldg((const float4*)(feat_a + (size_t)g * DD) + lane);
        float4 b = __ldg((const float4*)(feat_b + (size_t)g * DD) + lane);
        aa.x += a.x; aa.y += a.y; aa.z += a.z; aa.w += a.w;
        ab.x += b.x * w; ab.y += b.y * w; ab.z += b.z * w; ab.w += b.w * w;
    }
    int deg = end - start;
    float inv = 1.0f / (deg > 1 ? (float)deg : 1.0f);
    float4 oa = make_float4(aa.x * inv, aa.y * inv, aa.z * inv, aa.w * inv);
    float4 ob = make_float4(ab.x * inv, ab.y * inv, ab.z * inv, ab.w * inv);
    ((float4*)(out_a + (size_t)n * DD))[lane] = oa;
    ((float4*)(out_b + (size_t)n * DD))[lane] = ob;
}

// ---------------- GEMM: y = relu(x @ W^T + b), in place (x already mean) ----------------
#define GEMM_SMEM (64 * 128 * 4 + 129 * 128 * 4)

__device__ __forceinline__ void ffma2(unsigned long long& d, unsigned long long a,
                                      unsigned long long b) {
    asm("fma.rn.f32x2 %0, %1, %2, %0;" : "+l"(d) : "l"(a), "l"(b));
}
__device__ __forceinline__ unsigned long long pack2(float lo, float hi) {
    unsigned long long r;
    asm("mov.b64 %0, {%1, %2};" : "=l"(r) : "f"(lo), "f"(hi));
    return r;
}
__device__ __forceinline__ void unpack2(unsigned long long v, float& lo, float& hi) {
    asm("mov.b64 {%0, %1}, %2;" : "=f"(lo), "=f"(hi) : "l"(v));
}

__global__ void k_gemm_relu(float* __restrict__ xio,
                            const float* __restrict__ W,
                            const float* __restrict__ bias,
                            int N)
{
    extern __shared__ float sm[];
    float* xs = sm;              // [64][128]
    float* ws = sm + 64 * 128;   // [128][129] transposed W
    int tx = threadIdx.x, ty = threadIdx.y;
    int tid = ty * 32 + tx;
    int row0 = blockIdx.x * 64;

    for (int idx = tid; idx < 128 * 128; idx += 256) {
        int i = idx >> 7, k = idx & 127;
        ws[k * 129 + i] = __ldg(W + idx);
    }
    for (int idx = tid; idx < 64 * 32; idx += 256) {
        int r = idx >> 5;
        int row = row0 + r;
        float4 v = make_float4(0.f, 0.f, 0.f, 0.f);
        if (row < N) v = ((const float4*)(xio + (size_t)row * DD))[idx & 31];
        ((float4*)xs)[idx] = v;
    }
    __syncthreads();

    unsigned long long accA[8], accB[8];
#pragma unroll
    for (int r = 0; r < 8; r++) { accA[r] = 0ull; accB[r] = 0ull; }

#pragma unroll 4
    for (int k = 0; k < 128; k++) {
        float b0 = ws[k * 129 + tx];
        float b1 = ws[k * 129 + tx + 32];
        float b2 = ws[k * 129 + tx + 64];
        float b3 = ws[k * 129 + tx + 96];
        unsigned long long bA = pack2(b0, b1);
        unsigned long long bB = pack2(b2, b3);
#pragma unroll
        for (int r = 0; r < 8; r++) {
            float a = xs[(ty * 8 + r) * 128 + k];
            unsigned long long aa = pack2(a, a);
            ffma2(accA[r], aa, bA);
            ffma2(accB[r], aa, bB);
        }
    }

    float bb0 = __ldg(bias + tx);
    float bb1 = __ldg(bias + tx + 32);
    float bb2 = __ldg(bias + tx + 64);
    float bb3 = __ldg(bias + tx + 96);
#pragma unroll
    for (int r = 0; r < 8; r++) {
        int row = row0 + ty * 8 + r;
        if (row < N) {
            float a0, a1, a2, a3;
            unpack2(accA[r], a0, a1);
            unpack2(accB[r], a2, a3);
            float* yr = xio + (size_t)row * DD;
            yr[tx]      = fmaxf(a0 + bb0, 0.f);
            yr[tx + 32] = fmaxf(a1 + bb1, 0.f);
            yr[tx + 64] = fmaxf(a2 + bb2, 0.f);
            yr[tx + 96] = fmaxf(a3 + bb3, 0.f);
        }
    }
}

// ---------------- attention combine ----------------
__global__ void k_att(const float* __restrict__ y1,
                      const float* __restrict__ y2,
                      const float* __restrict__ y3,
                      const float* __restrict__ att,
                      float* __restrict__ out,
                      int N)
{
    int t = blockIdx.x * blockDim.x + threadIdx.x;
    int n = t >> 5, lane = t & 31;
    if (n >= N) return;
    size_t base = (size_t)n * DD;
    float4 v1 = __ldg((const float4*)(y1 + base) + lane);
    float4 v2 = __ldg((const float4*)(y2 + base) + lane);
    float4 v3 = __ldg((const float4*)(y3 + base) + lane);
    float4 a1 = __ldg((const float4*)att + lane);
    float4 a2 = __ldg((const float4*)att + 32 + lane);
    float4 a3 = __ldg((const float4*)att + 64 + lane);

    float s1 = v1.x * a1.x + v1.y * a1.y + v1.z * a1.z + v1.w * a1.w;
    float s2 = v2.x * a2.x + v2.y * a2.y + v2.z * a2.z + v2.w * a2.w;
    float s3 = v3.x * a3.x + v3.y * a3.y + v3.z * a3.z + v3.w * a3.w;
#pragma unroll
    for (int off = 16; off; off >>= 1) {
        s1 += __shfl_xor_sync(0xFFFFFFFFu, s1, off);
        s2 += __shfl_xor_sync(0xFFFFFFFFu, s2, off);
        s3 += __shfl_xor_sync(0xFFFFFFFFu, s3, off);
    }
    float m = fmaxf(s1, fmaxf(s2, s3));
    float e1 = __expf(s1 - m), e2 = __expf(s2 - m), e3 = __expf(s3 - m);
    float inv = 1.0f / (e1 + e2 + e3);
    float w1 = e1 * inv, w2 = e2 * inv, w3 = e3 * inv;

    float4 o;
    o.x = w1 * v1.x + w2 * v2.x + w3 * v3.x;
    o.y = w1 * v1.y + w2 * v2.y + w3 * v3.y;
    o.z = w1 * v1.z + w2 * v2.z + w3 * v3.z;
    o.w = w1 * v1.w + w2 * v2.w + w3 * v3.w;
    ((float4*)(out + base))[lane] = o;
}

// ---------------- launch ----------------
static inline int cdiv(long long a, int b) { return (int)((a + b - 1) / b); }

extern "C" void kernel_launch(void* const* d_in, const int* in_sizes, int n_in,
                              void* d_out, int out_size)
{
    const float* x_node   = (const float*)d_in[0];
    const float* x1       = (const float*)d_in[1];
    const float* x2       = (const float*)d_in[2];
    const int*   ei1_src  = (const int*)d_in[3];
    const int*   ei1_dst  = (const int*)d_in[4];
    const int*   ei2_src  = (const int*)d_in[5];
    const int*   ei2_dst  = (const int*)d_in[6];
    const int*   ei12_src = (const int*)d_in[7];
    const int*   ei12_dst = (const int*)d_in[8];
    const float* ew1      = (const float*)d_in[9];
    const float* ew2      = (const float*)d_in[10];
    const float* W1       = (const float*)d_in[11];
    const float* b1       = (const float*)d_in[12];
    const float* W2       = (const float*)d_in[13];
    const float* b2       = (const float*)d_in[14];
    const float* W12      = (const float*)d_in[15];
    const float* b12      = (const float*)d_in[16];
    const float* att      = (const float*)d_in[17];
    float* out = (float*)d_out;

    int n0  = in_sizes[0] / DD;
    int n1  = in_sizes[1] / DD;
    int n2  = in_sizes[2] / DD;
    int e1  = in_sizes[3];
    int e2  = in_sizes[5];
    int e12 = in_sizes[7];

    float *net1, *net2, *net2b, *s1, *s2, *s12;
    int *rowptr, *cursor;
    int *p1g, *p2g, *pb1g, *pcg, *pb2g;
    float *p1w, *p2w, *pb2w;
    cudaGetSymbolAddress((void**)&net1,  g_net1);
    cudaGetSymbolAddress((void**)&net2,  g_net2);
    cudaGetSymbolAddress((void**)&net2b, g_net2b);
    cudaGetSymbolAddress((void**)&s1,  g_s1);
    cudaGetSymbolAddress((void**)&s2,  g_s2);
    cudaGetSymbolAddress((void**)&s12, g_s12);
    cudaGetSymbolAddress((void**)&rowptr, g_rowptr);
    cudaGetSymbolAddress((void**)&cursor, g_cursor);
    cudaGetSymbolAddress((void**)&p1g,  g_p1g);
    cudaGetSymbolAddress((void**)&p1w,  g_p1w);
    cudaGetSymbolAddress((void**)&p2g,  g_p2g);
    cudaGetSymbolAddress((void**)&p2w,  g_p2w);
    cudaGetSymbolAddress((void**)&pb1g, g_pb1g);
    cudaGetSymbolAddress((void**)&pcg,  g_pcg);
    cudaGetSymbolAddress((void**)&pb2g, g_pb2g);
    cudaGetSymbolAddress((void**)&pb2w, g_pb2w);

    cudaFuncSetAttribute(k_gemm_relu, cudaFuncAttributeMaxDynamicSharedMemorySize, GEMM_SMEM);

    // zero only histograms (1.2MB)
    cudaMemsetAsync(cursor, 0, (size_t)RPTOT * sizeof(int), 0);

    const int BT = 256;

    // --- histograms ---
    k_hist<<<cdiv(e1, BT), BT>>>(ei1_dst,  cursor + RP1,  e1);
    k_hist<<<cdiv(e2, BT), BT>>>(ei2_dst,  cursor + RP2,  e2);
    k_hist<<<cdiv(e1, BT), BT>>>(ei1_src,  cursor + RPB1, e1);
    k_hist<<<cdiv(e12, BT), BT>>>(ei12_dst, cursor + RPC,  e12);
    k_hist<<<cdiv(e2, BT), BT>>>(ei2_src,  cursor + RPB2, e2);

    // --- fused scans (5 blocks, one per CSR) ---
    Seg5 segs;
    segs.off[0] = RP1;  segs.n[0] = n1;
    segs.off[1] = RP2;  segs.n[1] = n2;
    segs.off[2] = RPB1; segs.n[2] = n0;
    segs.off[3] = RPC;  segs.n[3] = n2;
    segs.off[4] = RPB2; segs.n[4] = n0;
    k_scan5<<<5, 1024>>>(rowptr, cursor, segs);

    // --- binning ---
    k_bin<<<cdiv(e1, BT), BT>>>(ei1_dst,  ei1_src,  ew1, cursor + RP1,  p1g,  p1w,  e1);
    k_bin<<<cdiv(e2, BT), BT>>>(ei2_dst,  ei2_src,  ew2, cursor + RP2,  p2g,  p2w,  e2);
    k_bin<<<cdiv(e1, BT), BT>>>(ei1_src,  ei1_dst,  (const float*)0, cursor + RPB1, pb1g, (float*)0, e1);
    k_bin<<<cdiv(e12, BT), BT>>>(ei12_dst, ei12_src, (const float*)0, cursor + RPC,  pcg,  (float*)0, e12);
    k_bin<<<cdiv(e2, BT), BT>>>(ei2_src,  ei2_dst,  ew2, cursor + RPB2, pb2g, pb2w, e2);

    // --- gathers (atomic-free) ---
    // net1 = (mean(x_node[src]*ew1 by dst) + x1)*0.5
    k_gather_msg<<<cdiv((long long)n1 * 32, BT), BT>>>(x_node, p1g, p1w, rowptr + RP1, x1, net1, n1);
    // net2 = (mean(x_node[src]*ew2 by dst) + x2)*0.5
    k_gather_msg<<<cdiv((long long)n2 * 32, BT), BT>>>(x_node, p2g, p2w, rowptr + RP2, x2, net2, n2);
    // s1 = mean(net1[dst] by src)
    k_gather_s<<<cdiv((long long)n0 * 32, BT), BT>>>(net1, pb1g, rowptr + RPB1, s1, n0);
    // net2b = (mean(net1[ei12_src] by ei12_dst) + x2)*0.5
    k_gather_msg<<<cdiv((long long)n2 * 32, BT), BT>>>(net1, pcg, (const float*)0, rowptr + RPC, x2, net2b, n2);
    // s2 = mean(net2[dst] by src); s12 = mean(net2b[dst]*ew2 by src)
    k_gather_dual<<<cdiv((long long)n0 * 32, BT), BT>>>(net2, net2b, pb2g, pb2w, rowptr + RPB2, s2, s12, n0);

    // --- GEMM + ReLU (in place) ---
    dim3 gblk(32, 8);
    k_gemm_relu<<<cdiv(n0, 64), gblk, GEMM_SMEM>>>(s1,  W1,  b1,  n0);
    k_gemm_relu<<<cdiv(n0, 64), gblk, GEMM_SMEM>>>(s2,  W2,  b2,  n0);
    k_gemm_relu<<<cdiv(n0, 64), gblk, GEMM_SMEM>>>(s12, W12, b12, n0);

    // --- attention combine ---
    k_att<<<cdiv((long long)n0 * 32, BT), BT>>>(s1, s2, s12, att, out, n0);
}